// round 13
// baseline (speedup 1.0000x reference)
#include <cuda_runtime.h>
#include <cuda_bf16.h>
#include <cuda_fp16.h>
#include <math.h>

#define BATCH  2
#define CDIM   512
#define NTOK   4096
#define HEADS  8
#define HD     64
#define GROUPS 32

// ---------------- scratch (static device globals; no allocations) ----------
__device__ __nv_bfloat16 g_hb[(size_t)BATCH*NTOK*CDIM];   // GN out, [B][N][C]
__device__ __nv_bfloat16 g_qb[(size_t)BATCH*NTOK*CDIM];   // Q (pre-scaled), [B][N][C]
__device__ __nv_bfloat16 g_kb[(size_t)BATCH*NTOK*CDIM];   // K, [B][N][C]
__device__ __half        g_vh[(size_t)BATCH*CDIM*NTOK];   // V, [B][C][N], f16
__device__ float g_o [(size_t)BATCH*CDIM*NTOK];           // attn out, [B][C][N]
__device__ float g_wt[(size_t)CDIM*CDIM];                 // Wo^T fp32 [k][m]
__device__ __nv_bfloat16 g_wb[3*(size_t)CDIM*CDIM];       // Wq,Wk,Wv bf16 [c][k]
__device__ float g_gnstat[BATCH*GROUPS*2];                // per-(b,g) mean, rstd

// ---------------- helpers ---------------------------------------------------
__device__ __forceinline__ float tf32r(float x) {
    asm("cvt.rna.tf32.f32 %0, %0;" : "+f"(x));
    return x;
}

__device__ __forceinline__ void mma_tf32(float& d0, float& d1, float& d2, float& d3,
                                         float a0, float a1, float a2, float a3,
                                         float b0, float b1)
{
    asm volatile("mma.sync.aligned.m16n8k8.row.col.f32.tf32.tf32.f32 "
                 "{%0,%1,%2,%3},{%4,%5,%6,%7},{%8,%9},{%0,%1,%2,%3};"
                 : "+f"(d0), "+f"(d1), "+f"(d2), "+f"(d3)
                 : "f"(a0), "f"(a1), "f"(a2), "f"(a3), "f"(b0), "f"(b1));
}

__device__ __forceinline__ void mma_bf16(float& d0, float& d1, float& d2, float& d3,
                                         unsigned a0, unsigned a1, unsigned a2, unsigned a3,
                                         unsigned b0, unsigned b1)
{
    asm volatile("mma.sync.aligned.m16n8k16.row.col.f32.bf16.bf16.f32 "
                 "{%0,%1,%2,%3},{%4,%5,%6,%7},{%8,%9},{%0,%1,%2,%3};"
                 : "+f"(d0), "+f"(d1), "+f"(d2), "+f"(d3)
                 : "r"(a0), "r"(a1), "r"(a2), "r"(a3), "r"(b0), "r"(b1));
}

__device__ __forceinline__ void mma_f16(float& d0, float& d1, float& d2, float& d3,
                                        unsigned a0, unsigned a1, unsigned a2, unsigned a3,
                                        unsigned b0, unsigned b1)
{
    asm volatile("mma.sync.aligned.m16n8k16.row.col.f32.f16.f16.f32 "
                 "{%0,%1,%2,%3},{%4,%5,%6,%7},{%8,%9},{%0,%1,%2,%3};"
                 : "+f"(d0), "+f"(d1), "+f"(d2), "+f"(d3)
                 : "r"(a0), "r"(a1), "r"(a2), "r"(a3), "r"(b0), "r"(b1));
}

__device__ __forceinline__ void ldsm4(unsigned& r0, unsigned& r1, unsigned& r2,
                                      unsigned& r3, unsigned a)
{
    asm volatile("ldmatrix.sync.aligned.m8n8.x4.shared.b16 {%0,%1,%2,%3}, [%4];"
                 : "=r"(r0), "=r"(r1), "=r"(r2), "=r"(r3) : "r"(a));
}

__device__ __forceinline__ unsigned packbf(float lo, float hi) {
    __nv_bfloat162 p = __floats2bfloat162_rn(lo, hi);
    return *(unsigned*)&p;
}

// exp2 of two f32 values -> packed f16x2, via ONE MUFU instruction
__device__ __forceinline__ unsigned exp2h2(float lo, float hi) {
    unsigned d;
    asm("{\n\t.reg .b32 t;\n\t"
        "cvt.rn.f16x2.f32 t, %2, %1;\n\t"
        "ex2.approx.f16x2 %0, t;\n\t}"
        : "=r"(d) : "f"(lo), "f"(hi));
    return d;
}

__device__ __forceinline__ unsigned hadd2u(unsigned a, unsigned b) {
    unsigned d;
    asm("add.f16x2 %0, %1, %2;" : "=r"(d) : "r"(a), "r"(b));
    return d;
}

__device__ __forceinline__ void cpa16(unsigned dst, const void* src) {
    asm volatile("cp.async.ca.shared.global [%0], [%1], 16;" :: "r"(dst), "l"(src));
}
#define CP_COMMIT() asm volatile("cp.async.commit_group;")
#define CP_WAIT1()  asm volatile("cp.async.wait_group 1;")
#define CP_WAIT0()  asm volatile("cp.async.wait_group 0;")

// ---------------- weight prep (merged convert + transpose) ------------------
__global__ void k_wprep(const float* __restrict__ W0, const float* __restrict__ W1,
                        const float* __restrict__ W2, const float* __restrict__ W3)
{
    int z = blockIdx.z;
    int tx = threadIdx.x, ty = threadIdx.y;
    if (z < 3) {
        const float* srcs[3] = {W0, W1, W2};
        const float* W = srcs[z];
        __nv_bfloat16* dst = g_wb + (size_t)z * CDIM * CDIM;
        int x = blockIdx.x * 32 + tx;
        int y = blockIdx.y * 32 + ty;
#pragma unroll
        for (int i = 0; i < 32; i += 8)
            dst[(size_t)(y + i) * CDIM + x] = __float2bfloat16(W[(size_t)(y + i) * CDIM + x]);
    } else {
        __shared__ float tile[32][33];
        int x = blockIdx.x * 32 + tx;
        int y = blockIdx.y * 32 + ty;
#pragma unroll
        for (int i = 0; i < 32; i += 8)
            tile[ty + i][tx] = W3[(size_t)(y + i) * CDIM + x];
        __syncthreads();
        int x2 = blockIdx.y * 32 + tx;
        int y2 = blockIdx.x * 32 + ty;
#pragma unroll
        for (int i = 0; i < 32; i += 8)
            g_wt[(size_t)(y2 + i) * CDIM + x2] = tile[tx][ty + i];
    }
}

// ---------------- GroupNorm stats: one block per (b, g) ---------------------
__global__ void k_gn_stats(const float* __restrict__ x)
{
    int bg = blockIdx.x;
    int b = bg >> 5, g = bg & 31;
    size_t base = ((size_t)b * CDIM + g * 16) * NTOK;
    const float4* xp = (const float4*)(x + base);

    float s = 0.f, ss = 0.f;
    for (int i = threadIdx.x; i < 16384; i += 256) {
        float4 v = xp[i];
        s  += v.x + v.y + v.z + v.w;
        ss += v.x*v.x + v.y*v.y + v.z*v.z + v.w*v.w;
    }
#pragma unroll
    for (int off = 16; off > 0; off >>= 1) {
        s  += __shfl_xor_sync(0xffffffffu, s,  off);
        ss += __shfl_xor_sync(0xffffffffu, ss, off);
    }
    __shared__ float red[16];
    int warp = threadIdx.x >> 5;
    if ((threadIdx.x & 31) == 0) { red[warp] = s; red[8 + warp] = ss; }
    __syncthreads();
    if (threadIdx.x == 0) {
        float S = 0.f, SS = 0.f;
        for (int w = 0; w < 8; w++) { S += red[w]; SS += red[8 + w]; }
        float mean = S * (1.0f / 65536.0f);
        float var  = SS * (1.0f / 65536.0f) - mean * mean;
        g_gnstat[bg * 2]     = mean;
        g_gnstat[bg * 2 + 1] = rsqrtf(var + 1e-5f);
    }
}

// ---------------- GroupNorm apply: 1024 blocks, streaming -------------------
__global__ void k_gn_apply(const float* __restrict__ x,
                           const float* __restrict__ gamma,
                           const float* __restrict__ beta)
{
    int bg = blockIdx.y;
    int b = bg >> 5, g = bg & 31;
    float mean = g_gnstat[bg * 2];
    float rstd = g_gnstat[bg * 2 + 1];

    float ga[16], be[16];
#pragma unroll
    for (int c = 0; c < 16; c++) {
        ga[c] = gamma[g * 16 + c] * rstd;
        be[c] = beta[g * 16 + c] - mean * ga[c];
    }

    const float* xc = x + ((size_t)b * CDIM + g * 16) * NTOK;
    __nv_bfloat16* hb = g_hb + (size_t)b * NTOK * CDIM + g * 16;
    int t = blockIdx.x * 256 + threadIdx.x;

    unsigned w[8];
#pragma unroll
    for (int c2 = 0; c2 < 8; c2++) {
        float v0 = xc[(size_t)(2 * c2) * NTOK + t];
        float v1 = xc[(size_t)(2 * c2 + 1) * NTOK + t];
        w[c2] = packbf(v0 * ga[2 * c2] + be[2 * c2],
                       v1 * ga[2 * c2 + 1] + be[2 * c2 + 1]);
    }
    uint4* dst = (uint4*)(hb + (size_t)t * CDIM);
    dst[0] = make_uint4(w[0], w[1], w[2], w[3]);
    dst[1] = make_uint4(w[4], w[5], w[6], w[7]);
}

// ---------------- fused QKV GEMM (bf16, K-tile 32, 3 stages, ldmatrix) ------
#define QSTG 25600

__device__ __forceinline__ void qkv_stage(unsigned sbase, const __nv_bfloat16* A,
                                          int t0, int c0, int k0, int bf, int tid)
{
    unsigned dst = sbase + bf * QSTG;
    int row = tid >> 1, hf = tid & 1;
    const __nv_bfloat16* as = A + (size_t)(t0 + row) * CDIM + k0 + hf * 16;
    cpa16(dst + row * 80 + hf * 32, as);
    cpa16(dst + row * 80 + hf * 32 + 16, as + 8);
#pragma unroll
    for (int c = tid; c < 768; c += 256) {
        int wi = c >> 8, idx = c & 255, rr = idx >> 2, ch = idx & 3;
        cpa16(dst + 10240 + wi * 5120 + rr * 80 + ch * 16,
              g_wb + (size_t)wi * CDIM * CDIM + (size_t)(c0 + rr) * CDIM + k0 + ch * 8);
    }
}

__global__ void __launch_bounds__(256) k_qkv(const float* __restrict__ bq,
                                             const float* __restrict__ bk,
                                             const float* __restrict__ bv,
                                             float scl)
{
    extern __shared__ __align__(16) unsigned char smraw[];   // 3*QSTG dynamic
    float* Cs = (float*)smraw;

    int b  = blockIdx.z;
    int t0 = blockIdx.x * 128;
    int c0 = blockIdx.y * 64;

    const __nv_bfloat16* A = g_hb + (size_t)b * NTOK * CDIM;   // [t][k]

    int tid  = threadIdx.x;
    int lane = tid & 31, warp = tid >> 5;
    int r = lane >> 2, q = lane & 3;
    int wm = (warp & 3) * 32;
    int wn = (warp >> 2) * 32;

    float acc[3][2][4][4];
#pragma unroll
    for (int w = 0; w < 3; w++)
#pragma unroll
        for (int i = 0; i < 2; i++)
#pragma unroll
            for (int j = 0; j < 4; j++)
#pragma unroll
                for (int k = 0; k < 4; k++) acc[w][i][j][k] = 0.f;

    unsigned sbase = (unsigned)__cvta_generic_to_shared(smraw);

    unsigned aoff = ((lane & 7) + ((lane >> 3) & 1) * 8) * 80 + ((lane >> 4) & 1) * 16;
    unsigned woff = (((lane >> 4) & 1) * 8 + (lane & 7)) * 80 + ((lane >> 3) & 1) * 16;

    qkv_stage(sbase, A, t0, c0, 0,  0, tid); CP_COMMIT();
    qkv_stage(sbase, A, t0, c0, 32, 1, tid); CP_COMMIT();

    for (int kit = 0; kit < CDIM / 32; kit++) {
        CP_WAIT1();
        __syncthreads();

        int k2 = (kit + 2) * 32;
        if (k2 < CDIM)
            qkv_stage(sbase, A, t0, c0, k2, (kit + 2) % 3, tid);
        CP_COMMIT();

        unsigned bufb = sbase + (kit % 3) * QSTG;
#pragma unroll
        for (int ks = 0; ks < 2; ks++) {
            unsigned a[2][4];
#pragma unroll
            for (int ms = 0; ms < 2; ms++)
                ldsm4(a[ms][0], a[ms][1], a[ms][2], a[ms][3],
                      bufb + (wm + ms * 16) * 80 + ks * 32 + aoff);
#pragma unroll
            for (int wi = 0; wi < 3; wi++) {
#pragma unroll
                for (int np = 0; np < 2; np++) {
                    unsigned w0, w1, w2, w3;
                    ldsm4(w0, w1, w2, w3,
                          bufb + 10240 + wi * 5120 + (wn + np * 16) * 80 + ks * 32 + woff);
#pragma unroll
                    for (int ms = 0; ms < 2; ms++) {
                        mma_bf16(acc[wi][ms][2*np][0], acc[wi][ms][2*np][1],
                                 acc[wi][ms][2*np][2], acc[wi][ms][2*np][3],
                                 a[ms][0], a[ms][1], a[ms][2], a[ms][3], w0, w1);
                        mma_bf16(acc[wi][ms][2*np+1][0], acc[wi][ms][2*np+1][1],
                                 acc[wi][ms][2*np+1][2], acc[wi][ms][2*np+1][3],
                                 a[ms][0], a[ms][1], a[ms][2], a[ms][3], w2, w3);
                    }
                }
            }
        }
    }

    // ---- Q and K: direct row-major bf16 stores ----
#pragma unroll
    for (int wi = 0; wi < 2; wi++) {
        const float* bias = (wi == 0 ? bq : bk);
        float osc = (wi == 0 ? scl : 1.0f);
        __nv_bfloat16* Y = (wi == 0 ? g_qb : g_kb);
#pragma unroll
        for (int nt = 0; nt < 4; nt++) {
            float2 bi = *(const float2*)&bias[c0 + wn + nt * 8 + 2 * q];
#pragma unroll
            for (int ms = 0; ms < 2; ms++) {
                size_t row0 = (size_t)b * NTOK + t0 + wm + ms * 16 + r;
                int ch = c0 + wn + nt * 8 + 2 * q;
                *(__nv_bfloat162*)&Y[row0 * CDIM + ch] =
                    __floats2bfloat162_rn((acc[wi][ms][nt][0] + bi.x) * osc,
                                          (acc[wi][ms][nt][1] + bi.y) * osc);
                *(__nv_bfloat162*)&Y[(row0 + 8) * CDIM + ch] =
                    __floats2bfloat162_rn((acc[wi][ms][nt][2] + bi.x) * osc,
                                          (acc[wi][ms][nt][3] + bi.y) * osc);
            }
        }
    }

    // ---- V: smem-staged transpose to [B][C][N] f16 ----
    CP_WAIT0();
    __syncthreads();
#pragma unroll
    for (int ms = 0; ms < 2; ms++) {
        int rowL = wm + ms * 16 + r;
#pragma unroll
        for (int nt = 0; nt < 4; nt++) {
            int chL = wn + nt * 8 + 2 * q;
            float2 bi = *(const float2*)&bv[c0 + chL];
            Cs[rowL * 65 + chL]           = acc[2][ms][nt][0] + bi.x;
            Cs[rowL * 65 + chL + 1]       = acc[2][ms][nt][1] + bi.y;
            Cs[(rowL + 8) * 65 + chL]     = acc[2][ms][nt][2] + bi.x;
            Cs[(rowL + 8) * 65 + chL + 1] = acc[2][ms][nt][3] + bi.y;
        }
    }
    __syncthreads();
    for (int e = tid; e < 8192; e += 256) {
        int cL = e >> 7, nL = e & 127;
        g_vh[((size_t)b * CDIM + c0 + cL) * NTOK + t0 + nL] =
            __float2half(Cs[nL * 65 + cL]);
    }
}

// ---------------- output GEMM (tf32, 3-stage, one sync/iter) ----------------
#define ASTR 136
#define BSTR 72
#define OBUF 13312

__global__ void __launch_bounds__(256) k_gemm_out(const float* __restrict__ bias,
                                                  const float* __restrict__ resid,
                                                  float* __restrict__ outp)
{
    int b  = blockIdx.z;
    int t0 = blockIdx.x * 128;
    int c0 = blockIdx.y * 64;

    const float* A  = g_o + (size_t)b * CDIM * NTOK;   // [k][t]
    const float* Wt = g_wt;                            // [k][c]

    __shared__ __align__(16) unsigned char smraw[3 * OBUF];
    float* Cs = (float*)smraw;

    int tid  = threadIdx.x;
    int lane = tid & 31, warp = tid >> 5;
    int r = lane >> 2, q = lane & 3;
    int wm = (warp & 3) * 32;
    int wn = (warp >> 2) * 32;

    float acc[2][4][4];
#pragma unroll
    for (int i = 0; i < 2; i++)
#pragma unroll
        for (int j = 0; j < 4; j++)
#pragma unroll
            for (int k = 0; k < 4; k++) acc[i][j][k] = 0.f;

    unsigned sbase = (unsigned)__cvta_generic_to_shared(smraw);

#pragma unroll
    for (int p = 0; p < 2; p++) {
        int k0 = p * 16;
#pragma unroll
        for (int c = tid; c < 512; c += 256) {
            int kr = c >> 5, seg = c & 31;
            cpa16(sbase + p * OBUF + kr * 544 + seg * 16,
                  A + (size_t)(k0 + kr) * NTOK + t0 + seg * 4);
        }
        {
            int kr = tid >> 4, seg = tid & 15;
            cpa16(sbase + p * OBUF + 8704 + kr * 288 + seg * 16,
                  Wt + (size_t)(k0 + kr) * CDIM + c0 + seg * 4);
        }
        CP_COMMIT();
    }

    for (int kit = 0; kit < CDIM / 16; kit++) {
        CP_WAIT1();
        __syncthreads();
        int p = kit % 3;

        int k2 = (kit + 2) * 16;
        if (k2 < CDIM) {
            int pn = (kit + 2) % 3;
#pragma unroll
            for (int c = tid; c < 512; c += 256) {
                int kr = c >> 5, seg = c & 31;
                cpa16(sbase + pn * OBUF + kr * 544 + seg * 16,
                      A + (size_t)(k2 + kr) * NTOK + t0 + seg * 4);
            }
            int kr = tid >> 4, seg = tid & 15;
            cpa16(sbase + pn * OBUF + 8704 + kr * 288 + seg * 16,
                  Wt + (size_t)(k2 + kr) * CDIM + c0 + seg * 4);
        }
        CP_COMMIT();

        float* As = (float*)(smraw + p * OBUF);
        float* Bs = As + 2176;

#pragma unroll
        for (int ks = 0; ks < 2; ks++) {
            int k8 = ks * 8;
            float a[2][4], bb[4][2];
#pragma unroll
            for (int ms = 0; ms < 2; ms++) {
                int ml = wm + ms * 16;
                a[ms][0] = tf32r(As[(k8 + q) * ASTR + ml + r]);
                a[ms][1] = tf32r(As[(k8 + q) * ASTR + ml + r + 8]);
                a[ms][2] = tf32r(As[(k8 + q + 4) * ASTR + ml + r]);
                a[ms][3] = tf32r(As[(k8 + q + 4) * ASTR + ml + r + 8]);
            }
#pragma unroll
            for (int ns = 0; ns < 4; ns++) {
                int nl = wn + ns * 8;
                bb[ns][0] = tf32r(Bs[(k8 + q) * BSTR + nl + r]);
                bb[ns][1] = tf32r(Bs[(k8 + q + 4) * BSTR + nl + r]);
            }
#pragma unroll
            for (int ms = 0; ms < 2; ms++)
#pragma unroll
                for (int ns = 0; ns < 4; ns++)
                    mma_tf32(acc[ms][ns][0], acc[ms][ns][1], acc[ms][ns][2], acc[ms][ns][3],
                             a[ms][0], a[ms][1], a[ms][2], a[ms][3],
                             bb[ns][0], bb[ns][1]);
        }
    }

#pragma unroll
    for (int ns = 0; ns < 4; ns++) {
        float2 bi = *(const float2*)&bias[c0 + wn + ns * 8 + 2 * q];
#pragma unroll
        for (int ms = 0; ms < 2; ms++) {
            acc[ms][ns][0] += bi.x; acc[ms][ns][1] += bi.y;
            acc[ms][ns][2] += bi.x; acc[ms][ns][3] += bi.y;
        }
    }

    CP_WAIT0();
    __syncthreads();
#pragma unroll
    for (int ms = 0; ms < 2; ms++) {
        int rowL = wm + ms * 16 + r;
#pragma unroll
        for (int ns = 0; ns < 4; ns++) {
            int chL = wn + ns * 8 + 2 * q;
            Cs[rowL * 65 + chL]           = acc[ms][ns][0];
            Cs[rowL * 65 + chL + 1]       = acc[ms][ns][1];
            Cs[(rowL + 8) * 65 + chL]     = acc[ms][ns][2];
            Cs[(rowL + 8) * 65 + chL + 1] = acc[ms][ns][3];
        }
    }
    __syncthreads();
    for (int e = tid; e < 8192; e += 256) {
        int cL = e >> 7, nL = e & 127;
        size_t idx = ((size_t)b * CDIM + c0 + cL) * NTOK + t0 + nL;
        outp[idx] = Cs[nL * 65 + cL] + resid[idx];
    }
}

// ---------------- attention: hadd2 row sums (no ones-mma), 3-stage ----------
#define KW 36      // row stride in 32-bit words (144 B)
#define BUFB 18432

__global__ void __launch_bounds__(128, 3) k_attn()
{
    extern __shared__ __align__(16) unsigned char smraw[];   // 3*BUFB dynamic
    unsigned* Qw = (unsigned*)smraw;                 // [128][KW] (pre-loop only)
    float*    Es = (float*)smraw;                    // [64][71]  (epilogue only)

    int tid  = threadIdx.x;
    int lane = tid & 31, warp = tid >> 5;
    int r = lane >> 2, q = lane & 3;
    int n0 = blockIdx.x * 128;
    int h  = blockIdx.y;
    int b  = blockIdx.z;

    // ---- stage Q (bf16, pre-scaled by log2e/8 in GEMM) ----
    {
        const __nv_bfloat16* Qg = g_qb + ((size_t)b * NTOK + n0) * CDIM + h * HD;
#pragma unroll
        for (int it = 0; it < 8; it++) {
            uint4 v = *(const uint4*)&Qg[(size_t)tid * CDIM + it * 8];
            *(uint4*)&Qw[tid * KW + it * 4] = v;
        }
    }
    __syncthreads();

    unsigned aq[2][4][4];
#pragma unroll
    for (int mf = 0; mf < 2; mf++) {
        int rb = warp * 32 + mf * 16 + r;
#pragma unroll
        for (int kt = 0; kt < 4; kt++) {
            int base = kt * 8 + q;
            aq[mf][kt][0] = Qw[rb * KW + base];
            aq[mf][kt][1] = Qw[(rb + 8) * KW + base];
            aq[mf][kt][2] = Qw[rb * KW + base + 4];
            aq[mf][kt][3] = Qw[(rb + 8) * KW + base + 4];
        }
    }
    __syncthreads();

    float o[2][8][4];
#pragma unroll
    for (int mf = 0; mf < 2; mf++)
#pragma unroll
        for (int i = 0; i < 8; i++)
#pragma unroll
            for (int j = 0; j < 4; j++) o[mf][i][j] = 0.f;
    float lsum[2][2] = {{0.f, 0.f}, {0.f, 0.f}};   // [mf][row r / row r+8]

    const __nv_bfloat16* Kg = g_kb + (size_t)b * NTOK * CDIM + h * HD;
    const __half*        Vg = g_vh + ((size_t)b * CDIM + h * HD) * NTOK;

    int srow = tid >> 1, sh = tid & 1;
    unsigned sbase = (unsigned)__cvta_generic_to_shared(smraw);
    unsigned doff = srow * 144 + sh * 64;

    unsigned boff = (((lane >> 4) & 1) * 8 + (lane & 7)) * 144 + ((lane >> 3) & 1) * 16;

    // prefetch tiles 0 and 1
#pragma unroll
    for (int p = 0; p < 2; p++) {
        unsigned kd = sbase + p * BUFB + doff;
        const __nv_bfloat16* ksrc = Kg + (size_t)(p * 64 + srow) * CDIM + sh * 32;
        const __half*        vsrc = Vg + (size_t)srow * NTOK + p * 64 + sh * 32;
#pragma unroll
        for (int j = 0; j < 4; j++) {
            cpa16(kd + j * 16, ksrc + j * 8);
            cpa16(kd + 9216 + j * 16, vsrc + j * 8);
        }
        CP_COMMIT();
    }

    for (int it = 0; it < NTOK / 64; it++) {
        CP_WAIT1();
        __syncthreads();
        unsigned bufK = sbase + (it % 3) * BUFB;

        int jn = (it + 2) * 64;
        if (jn < NTOK) {
            unsigned kd = sbase + ((it + 2) % 3) * BUFB + doff;
            const __nv_bfloat16* ksrc = Kg + (size_t)(jn + srow) * CDIM + sh * 32;
            const __half*        vsrc = Vg + (size_t)srow * NTOK + jn + sh * 32;
#pragma unroll
            for (int j = 0; j < 4; j++) {
                cpa16(kd + j * 16, ksrc + j * 8);
                cpa16(kd + 9216 + j * 16, vsrc + j * 8);
            }
        }
        CP_COMMIT();

        // ---- S = Q * K^T (log2 space); K frags via ldmatrix.x4 ----
        float s[2][8][4];
#pragma unroll
        for (int mf = 0; mf < 2; mf++)
#pragma unroll
            for (int i = 0; i < 8; i++)
#pragma unroll
                for (int j = 0; j < 4; j++) s[mf][i][j] = 0.f;

#pragma unroll
        for (int kt = 0; kt < 4; kt++) {
            unsigned kab = bufK + kt * 32 + boff;
#pragma unroll
            for (int p = 0; p < 4; p++) {
                unsigned b0a, b1a, b0b, b1b;
                ldsm4(b0a, b1a, b0b, b1b, kab + p * 2304);
                mma_bf16(s[0][2*p][0], s[0][2*p][1], s[0][2*p][2], s[0][2*p][3],
                         aq[0][kt][0], aq[0][kt][1], aq[0][kt][2], aq[0][kt][3], b0a, b1a);
                mma_bf16(s[1][2*p][0], s[1][2*p][1], s[1][2*p][2], s[1][2*p][3],
                         aq[1][kt][0], aq[1][kt][1], aq[1][kt][2], aq[1][kt][3], b0a, b1a);
                mma_bf16(s[0][2*p+1][0], s[0][2*p+1][1], s[0][2*p+1][2], s[0][2*p+1][3],
                         aq[0][kt][0], aq[0][kt][1], aq[0][kt][2], aq[0][kt][3], b0b, b1b);
                mma_bf16(s[1][2*p+1][0], s[1][2*p+1][1], s[1][2*p+1][2], s[1][2*p+1][3],
                         aq[1][kt][0], aq[1][kt][1], aq[1][kt][2], aq[1][kt][3], b0b, b1b);
            }
        }

        // ---- P = exp2(S) packed f16; O += P*V; row sums via hadd2 ----
        unsigned hs[2][2] = {{0u, 0u}, {0u, 0u}};   // f16x2 partials [mf][row]
#pragma unroll
        for (int kt = 0; kt < 4; kt++) {
            unsigned pa[2][4];
#pragma unroll
            for (int mf = 0; mf < 2; mf++) {
                pa[mf][0] = exp2h2(s[mf][2*kt][0],     s[mf][2*kt][1]);
                pa[mf][1] = exp2h2(s[mf][2*kt][2],     s[mf][2*kt][3]);
                pa[mf][2] = exp2h2(s[mf][2*kt + 1][0], s[mf][2*kt + 1][1]);
                pa[mf][3] = exp2h2(s[mf][2*kt + 1][2], s[mf][2*kt + 1][3]);
                // pa0,pa2 belong to row r; pa1,pa3 to row r+8 (fma pipe)
                hs[mf][0] = hadd2u(hs[mf][0], hadd2u(pa[mf][0], pa[mf][2]));
                hs[mf][1] = hadd2u(hs[mf][1], hadd2u(pa[mf][1], pa[mf][3]));
            }
            unsigned vab = bufK + 9216 + kt * 32 + boff;
#pragma unroll
            for (int p = 0; p < 4; p++) {
                unsigned v0a, v1a, v0b, v1b;
                ldsm4(v0a, v1a, v0b, v1b, vab + p * 2304);
                mma_f16(o[0][2*p][0], o[0][2*p][1], o[0][2*p][2], o[0][2*p][3],
                        pa[0][0], pa[0][1], pa[0][2], pa[0][3], v0a, v1a);
                mma_f16(o[1][2*p][0], o[1][2*p][1], o[1][2*p][2], o[1][2*p][3],
                        pa[1][0], pa[1][1], pa[1][2], pa[1][3], v0a, v1a);
                mma_f16(o[0][2*p+1][0], o[0][2*p+1][1], o[0][2*p+1][2], o[0][2*p+1][3],
                        pa[0][0], pa[0][1], pa[0][2], pa[0][3], v0b, v1b);
                mma_f16(o[1][2*p+1][0], o[1][2*p+1][1], o[1][2*p+1][2], o[1][2*p+1][3],
                        pa[1][0], pa[1][1], pa[1][2], pa[1][3], v0b, v1b);
            }
        }
        // fold f16 partials to f32 each tile (bounded f16 error)
#pragma unroll
        for (int mf = 0; mf < 2; mf++)
#pragma unroll
            for (int rr = 0; rr < 2; rr++) {
                __half2 hv = *(__half2*)&hs[mf][rr];
                float2 fv = __half22float2(hv);
                lsum[mf][rr] += fv.x + fv.y;
            }
    }

    CP_WAIT0();
    __syncthreads();

    // reduce row sums across quad lanes (each q covers different columns)
#pragma unroll
    for (int mf = 0; mf < 2; mf++)
#pragma unroll
        for (int rr = 0; rr < 2; rr++) {
            lsum[mf][rr] += __shfl_xor_sync(0xffffffffu, lsum[mf][rr], 1);
            lsum[mf][rr] += __shfl_xor_sync(0xffffffffu, lsum[mf][rr], 2);
        }

    // ---- epilogue: normalize, two-phase smem transpose, write [B][C][N] ----
#pragma unroll
    for (int ph = 0; ph < 2; ph++) {
        if ((warp >> 1) == ph) {
#pragma unroll
            for (int mf = 0; mf < 2; mf++) {
                int rowL = (warp & 1) * 32 + mf * 16 + r;
                float il0 = 1.0f / lsum[mf][0], il1 = 1.0f / lsum[mf][1];
#pragma unroll
                for (int ct = 0; ct < 8; ct++) {
                    int cc = ct * 8 + 2 * q;
                    Es[rowL * 71 + cc]           = o[mf][ct][0] * il0;
                    Es[rowL * 71 + cc + 1]       = o[mf][ct][1] * il0;
                    Es[(rowL + 8) * 71 + cc]     = o[mf][ct][2] * il1;
                    Es[(rowL + 8) * 71 + cc + 1] = o[mf][ct][3] * il1;
                }
            }
        }
        __syncthreads();
        for (int e = tid; e < 4096; e += 128) {
            int c = e >> 6, n = e & 63;
            g_o[((size_t)b * CDIM + h * HD + c) * NTOK + n0 + ph * 64 + n] = Es[n * 71 + c];
        }
        __syncthreads();
    }
}

// ---------------- launch ----------------------------------------------------
extern "C" void kernel_launch(void* const* d_in, const int* in_sizes, int n_in,
                              void* d_out, int out_size)
{
    const float* x     = (const float*)d_in[0];
    const float* gamma = (const float*)d_in[1];
    const float* beta  = (const float*)d_in[2];
    const float* Wq    = (const float*)d_in[3];
    const float* bq    = (const float*)d_in[4];
    const float* Wk    = (const float*)d_in[5];
    const float* bk    = (const float*)d_in[6];
    const float* Wv    = (const float*)d_in[7];
    const float* bv    = (const float*)d_in[8];
    const float* Wo    = (const float*)d_in[9];
    const float* bo    = (const float*)d_in[10];
    float* out = (float*)d_out;

    const float SCL = 0.125f * 1.4426950408889634f;   // (1/sqrt(hd)) * log2(e)

    static int attr_done = 0;
    if (!attr_done) {
        cudaFuncSetAttribute(k_qkv,  cudaFuncAttributeMaxDynamicSharedMemorySize, 3 * QSTG);
        cudaFuncSetAttribute(k_attn, cudaFuncAttributeMaxDynamicSharedMemorySize, 3 * BUFB);
        attr_done = 1;
    }

    k_wprep<<<dim3(CDIM/32, CDIM/32, 4), dim3(32, 8)>>>(Wq, Wk, Wv, Wo);
    k_gn_stats<<<BATCH * GROUPS, 256>>>(x);
    k_gn_apply<<<dim3(NTOK/256, BATCH*GROUPS), 256>>>(x, gamma, beta);

    k_qkv<<<dim3(NTOK/128, CDIM/64, BATCH), 256, 3 * QSTG>>>(bq, bk, bv, SCL);

    k_attn<<<dim3(NTOK / 128, HEADS, BATCH), 128, 3 * BUFB>>>();

    k_gemm_out<<<dim3(NTOK/128, CDIM/64, BATCH), 256>>>(bo, x, out);
}

// round 14
// speedup vs baseline: 1.0552x; 1.0552x over previous
#include <cuda_runtime.h>
#include <cuda_bf16.h>
#include <cuda_fp16.h>
#include <math.h>

#define BATCH  2
#define CDIM   512
#define NTOK   4096
#define HEADS  8
#define HD     64
#define GROUPS 32

// ---------------- scratch (static device globals; no allocations) ----------
__device__ __nv_bfloat16 g_hb[(size_t)BATCH*NTOK*CDIM];   // GN out, [B][N][C]
__device__ __nv_bfloat16 g_qb[(size_t)BATCH*NTOK*CDIM];   // Q (pre-scaled), [B][N][C]
__device__ __nv_bfloat16 g_kb[(size_t)BATCH*NTOK*CDIM];   // K, [B][N][C]
__device__ __half        g_vh[(size_t)BATCH*CDIM*NTOK];   // V, [B][C][N], f16
__device__ float g_o [(size_t)BATCH*CDIM*NTOK];           // attn out, [B][C][N]
__device__ float g_wt[(size_t)CDIM*CDIM];                 // Wo^T fp32 [k][m]
__device__ __nv_bfloat16 g_wb[3*(size_t)CDIM*CDIM];       // Wq,Wk,Wv bf16 [c][k]

// ---------------- helpers ---------------------------------------------------
__device__ __forceinline__ float tf32r(float x) {
    asm("cvt.rna.tf32.f32 %0, %0;" : "+f"(x));
    return x;
}

__device__ __forceinline__ void mma_tf32(float& d0, float& d1, float& d2, float& d3,
                                         float a0, float a1, float a2, float a3,
                                         float b0, float b1)
{
    asm volatile("mma.sync.aligned.m16n8k8.row.col.f32.tf32.tf32.f32 "
                 "{%0,%1,%2,%3},{%4,%5,%6,%7},{%8,%9},{%0,%1,%2,%3};"
                 : "+f"(d0), "+f"(d1), "+f"(d2), "+f"(d3)
                 : "f"(a0), "f"(a1), "f"(a2), "f"(a3), "f"(b0), "f"(b1));
}

__device__ __forceinline__ void mma_bf16(float& d0, float& d1, float& d2, float& d3,
                                         unsigned a0, unsigned a1, unsigned a2, unsigned a3,
                                         unsigned b0, unsigned b1)
{
    asm volatile("mma.sync.aligned.m16n8k16.row.col.f32.bf16.bf16.f32 "
                 "{%0,%1,%2,%3},{%4,%5,%6,%7},{%8,%9},{%0,%1,%2,%3};"
                 : "+f"(d0), "+f"(d1), "+f"(d2), "+f"(d3)
                 : "r"(a0), "r"(a1), "r"(a2), "r"(a3), "r"(b0), "r"(b1));
}

__device__ __forceinline__ void mma_f16(float& d0, float& d1, float& d2, float& d3,
                                        unsigned a0, unsigned a1, unsigned a2, unsigned a3,
                                        unsigned b0, unsigned b1)
{
    asm volatile("mma.sync.aligned.m16n8k16.row.col.f32.f16.f16.f32 "
                 "{%0,%1,%2,%3},{%4,%5,%6,%7},{%8,%9},{%0,%1,%2,%3};"
                 : "+f"(d0), "+f"(d1), "+f"(d2), "+f"(d3)
                 : "r"(a0), "r"(a1), "r"(a2), "r"(a3), "r"(b0), "r"(b1));
}

__device__ __forceinline__ void ldsm4(unsigned& r0, unsigned& r1, unsigned& r2,
                                      unsigned& r3, unsigned a)
{
    asm volatile("ldmatrix.sync.aligned.m8n8.x4.shared.b16 {%0,%1,%2,%3}, [%4];"
                 : "=r"(r0), "=r"(r1), "=r"(r2), "=r"(r3) : "r"(a));
}

__device__ __forceinline__ unsigned packbf(float lo, float hi) {
    __nv_bfloat162 p = __floats2bfloat162_rn(lo, hi);
    return *(unsigned*)&p;
}

// exp2 of two f32 values -> packed f16x2, via ONE MUFU instruction
__device__ __forceinline__ unsigned exp2h2(float lo, float hi) {
    unsigned d;
    asm("{\n\t.reg .b32 t;\n\t"
        "cvt.rn.f16x2.f32 t, %2, %1;\n\t"
        "ex2.approx.f16x2 %0, t;\n\t}"
        : "=r"(d) : "f"(lo), "f"(hi));
    return d;
}

__device__ __forceinline__ void cpa16(unsigned dst, const void* src) {
    asm volatile("cp.async.ca.shared.global [%0], [%1], 16;" :: "r"(dst), "l"(src));
}
#define CP_COMMIT() asm volatile("cp.async.commit_group;")
#define CP_WAIT1()  asm volatile("cp.async.wait_group 1;")
#define CP_WAIT0()  asm volatile("cp.async.wait_group 0;")

// ---------------- fused prep: GroupNorm (blocks 0..63) + weight prep --------
// blocks [0,64)        : GroupNorm for (b,g) = blockIdx.x
// blocks [64, 64+1024) : weight tile prep; z = tile / 256 selects Wq/Wk/Wv/Wo
__global__ void k_prep(const float* __restrict__ x,
                       const float* __restrict__ gamma,
                       const float* __restrict__ beta,
                       const float* __restrict__ W0, const float* __restrict__ W1,
                       const float* __restrict__ W2, const float* __restrict__ W3)
{
    __shared__ float red[18];
    __shared__ float tile[32][33];
    int tid = threadIdx.x;

    if (blockIdx.x >= 64) {
        // ---- weight prep: 1024 tiles of 32x32 ----
        int t = blockIdx.x - 64;
        int z = t >> 8;                   // 0..3
        int ti = t & 255;
        int bx = ti & 15, by = ti >> 4;   // 16x16 tiles of 32
        int tx = tid & 31, ty = tid >> 5; // 32x8 threads
        if (z < 3) {
            const float* srcs[3] = {W0, W1, W2};
            const float* W = srcs[z];
            __nv_bfloat16* dst = g_wb + (size_t)z * CDIM * CDIM;
            int xx = bx * 32 + tx, yy = by * 32 + ty;
#pragma unroll
            for (int i = 0; i < 32; i += 8)
                dst[(size_t)(yy + i) * CDIM + xx] =
                    __float2bfloat16(W[(size_t)(yy + i) * CDIM + xx]);
        } else {
            int xx = bx * 32 + tx, yy = by * 32 + ty;
#pragma unroll
            for (int i = 0; i < 32; i += 8)
                tile[ty + i][tx] = W3[(size_t)(yy + i) * CDIM + xx];
            __syncthreads();
            int x2 = by * 32 + tx, y2 = bx * 32 + ty;
#pragma unroll
            for (int i = 0; i < 32; i += 8)
                g_wt[(size_t)(y2 + i) * CDIM + x2] = tile[tx][ty + i];
        }
        return;
    }

    // ---- GroupNorm for (b, g) ----
    int b = blockIdx.x >> 5;
    int g = blockIdx.x & 31;
    size_t base = ((size_t)b * CDIM + g * 16) * NTOK;
    const float4* xp = (const float4*)(x + base);

    float s = 0.f, ss = 0.f;
    for (int i = tid; i < 16384; i += 256) {
        float4 v = xp[i];
        s  += v.x + v.y + v.z + v.w;
        ss += v.x*v.x + v.y*v.y + v.z*v.z + v.w*v.w;
    }
#pragma unroll
    for (int off = 16; off > 0; off >>= 1) {
        s  += __shfl_xor_sync(0xffffffffu, s,  off);
        ss += __shfl_xor_sync(0xffffffffu, ss, off);
    }
    int warp = tid >> 5;
    if ((tid & 31) == 0) { red[warp] = s; red[8 + warp] = ss; }
    __syncthreads();
    if (tid == 0) {
        float S = 0.f, SS = 0.f;
        for (int w = 0; w < 8; w++) { S += red[w]; SS += red[8 + w]; }
        float mean = S * (1.0f / 65536.0f);
        float var  = SS * (1.0f / 65536.0f) - mean * mean;
        red[16] = mean;
        red[17] = rsqrtf(var + 1e-5f);
    }
    __syncthreads();
    float mean = red[16], rstd = red[17];

    float ga[16], be[16];
#pragma unroll
    for (int c = 0; c < 16; c++) {
        ga[c] = gamma[g * 16 + c] * rstd;
        be[c] = beta[g * 16 + c] - mean * ga[c];
    }

    const float* xc = x + base;
    __nv_bfloat16* hb = g_hb + (size_t)b * NTOK * CDIM + g * 16;
    for (int t = tid; t < NTOK; t += 256) {
        unsigned w[8];
#pragma unroll
        for (int c2 = 0; c2 < 8; c2++) {
            float v0 = xc[(size_t)(2 * c2) * NTOK + t];
            float v1 = xc[(size_t)(2 * c2 + 1) * NTOK + t];
            w[c2] = packbf(v0 * ga[2 * c2] + be[2 * c2],
                           v1 * ga[2 * c2 + 1] + be[2 * c2 + 1]);
        }
        uint4* dst = (uint4*)(hb + (size_t)t * CDIM);
        dst[0] = make_uint4(w[0], w[1], w[2], w[3]);
        dst[1] = make_uint4(w[4], w[5], w[6], w[7]);
    }
}

// ---------------- fused QKV GEMM (bf16, K-tile 32, 3 stages, ldmatrix) ------
#define QSTG 25600

__device__ __forceinline__ void qkv_stage(unsigned sbase, const __nv_bfloat16* A,
                                          int t0, int c0, int k0, int bf, int tid)
{
    unsigned dst = sbase + bf * QSTG;
    int row = tid >> 1, hf = tid & 1;
    const __nv_bfloat16* as = A + (size_t)(t0 + row) * CDIM + k0 + hf * 16;
    cpa16(dst + row * 80 + hf * 32, as);
    cpa16(dst + row * 80 + hf * 32 + 16, as + 8);
#pragma unroll
    for (int c = tid; c < 768; c += 256) {
        int wi = c >> 8, idx = c & 255, rr = idx >> 2, ch = idx & 3;
        cpa16(dst + 10240 + wi * 5120 + rr * 80 + ch * 16,
              g_wb + (size_t)wi * CDIM * CDIM + (size_t)(c0 + rr) * CDIM + k0 + ch * 8);
    }
}

__global__ void __launch_bounds__(256) k_qkv(const float* __restrict__ bq,
                                             const float* __restrict__ bk,
                                             const float* __restrict__ bv,
                                             float scl)
{
    extern __shared__ __align__(16) unsigned char smraw[];   // 3*QSTG dynamic
    float* Cs = (float*)smraw;

    int b  = blockIdx.z;
    int t0 = blockIdx.x * 128;
    int c0 = blockIdx.y * 64;

    const __nv_bfloat16* A = g_hb + (size_t)b * NTOK * CDIM;   // [t][k]

    int tid  = threadIdx.x;
    int lane = tid & 31, warp = tid >> 5;
    int r = lane >> 2, q = lane & 3;
    int wm = (warp & 3) * 32;
    int wn = (warp >> 2) * 32;

    float acc[3][2][4][4];
#pragma unroll
    for (int w = 0; w < 3; w++)
#pragma unroll
        for (int i = 0; i < 2; i++)
#pragma unroll
            for (int j = 0; j < 4; j++)
#pragma unroll
                for (int k = 0; k < 4; k++) acc[w][i][j][k] = 0.f;

    unsigned sbase = (unsigned)__cvta_generic_to_shared(smraw);

    unsigned aoff = ((lane & 7) + ((lane >> 3) & 1) * 8) * 80 + ((lane >> 4) & 1) * 16;
    unsigned woff = (((lane >> 4) & 1) * 8 + (lane & 7)) * 80 + ((lane >> 3) & 1) * 16;

    qkv_stage(sbase, A, t0, c0, 0,  0, tid); CP_COMMIT();
    qkv_stage(sbase, A, t0, c0, 32, 1, tid); CP_COMMIT();

    for (int kit = 0; kit < CDIM / 32; kit++) {
        CP_WAIT1();
        __syncthreads();

        int k2 = (kit + 2) * 32;
        if (k2 < CDIM)
            qkv_stage(sbase, A, t0, c0, k2, (kit + 2) % 3, tid);
        CP_COMMIT();

        unsigned bufb = sbase + (kit % 3) * QSTG;
#pragma unroll
        for (int ks = 0; ks < 2; ks++) {
            unsigned a[2][4];
#pragma unroll
            for (int ms = 0; ms < 2; ms++)
                ldsm4(a[ms][0], a[ms][1], a[ms][2], a[ms][3],
                      bufb + (wm + ms * 16) * 80 + ks * 32 + aoff);
#pragma unroll
            for (int wi = 0; wi < 3; wi++) {
#pragma unroll
                for (int np = 0; np < 2; np++) {
                    unsigned w0, w1, w2, w3;
                    ldsm4(w0, w1, w2, w3,
                          bufb + 10240 + wi * 5120 + (wn + np * 16) * 80 + ks * 32 + woff);
#pragma unroll
                    for (int ms = 0; ms < 2; ms++) {
                        mma_bf16(acc[wi][ms][2*np][0], acc[wi][ms][2*np][1],
                                 acc[wi][ms][2*np][2], acc[wi][ms][2*np][3],
                                 a[ms][0], a[ms][1], a[ms][2], a[ms][3], w0, w1);
                        mma_bf16(acc[wi][ms][2*np+1][0], acc[wi][ms][2*np+1][1],
                                 acc[wi][ms][2*np+1][2], acc[wi][ms][2*np+1][3],
                                 a[ms][0], a[ms][1], a[ms][2], a[ms][3], w2, w3);
                    }
                }
            }
        }
    }

    // ---- Q and K: direct row-major bf16 stores ----
#pragma unroll
    for (int wi = 0; wi < 2; wi++) {
        const float* bias = (wi == 0 ? bq : bk);
        float osc = (wi == 0 ? scl : 1.0f);
        __nv_bfloat16* Y = (wi == 0 ? g_qb : g_kb);
#pragma unroll
        for (int nt = 0; nt < 4; nt++) {
            float2 bi = *(const float2*)&bias[c0 + wn + nt * 8 + 2 * q];
#pragma unroll
            for (int ms = 0; ms < 2; ms++) {
                size_t row0 = (size_t)b * NTOK + t0 + wm + ms * 16 + r;
                int ch = c0 + wn + nt * 8 + 2 * q;
                *(__nv_bfloat162*)&Y[row0 * CDIM + ch] =
                    __floats2bfloat162_rn((acc[wi][ms][nt][0] + bi.x) * osc,
                                          (acc[wi][ms][nt][1] + bi.y) * osc);
                *(__nv_bfloat162*)&Y[(row0 + 8) * CDIM + ch] =
                    __floats2bfloat162_rn((acc[wi][ms][nt][2] + bi.x) * osc,
                                          (acc[wi][ms][nt][3] + bi.y) * osc);
            }
        }
    }

    // ---- V: smem-staged transpose to [B][C][N] f16 ----
    CP_WAIT0();
    __syncthreads();
#pragma unroll
    for (int ms = 0; ms < 2; ms++) {
        int rowL = wm + ms * 16 + r;
#pragma unroll
        for (int nt = 0; nt < 4; nt++) {
            int chL = wn + nt * 8 + 2 * q;
            float2 bi = *(const float2*)&bv[c0 + chL];
            Cs[rowL * 65 + chL]           = acc[2][ms][nt][0] + bi.x;
            Cs[rowL * 65 + chL + 1]       = acc[2][ms][nt][1] + bi.y;
            Cs[(rowL + 8) * 65 + chL]     = acc[2][ms][nt][2] + bi.x;
            Cs[(rowL + 8) * 65 + chL + 1] = acc[2][ms][nt][3] + bi.y;
        }
    }
    __syncthreads();
    for (int e = tid; e < 8192; e += 256) {
        int cL = e >> 7, nL = e & 127;
        g_vh[((size_t)b * CDIM + c0 + cL) * NTOK + t0 + nL] =
            __float2half(Cs[nL * 65 + cL]);
    }
}

// ---------------- output GEMM (tf32, 3-stage, one sync/iter) ----------------
#define ASTR 136
#define BSTR 72
#define OBUF 13312

__global__ void __launch_bounds__(256) k_gemm_out(const float* __restrict__ bias,
                                                  const float* __restrict__ resid,
                                                  float* __restrict__ outp)
{
    int b  = blockIdx.z;
    int t0 = blockIdx.x * 128;
    int c0 = blockIdx.y * 64;

    const float* A  = g_o + (size_t)b * CDIM * NTOK;   // [k][t]
    const float* Wt = g_wt;                            // [k][c]

    __shared__ __align__(16) unsigned char smraw[3 * OBUF];
    float* Cs = (float*)smraw;

    int tid  = threadIdx.x;
    int lane = tid & 31, warp = tid >> 5;
    int r = lane >> 2, q = lane & 3;
    int wm = (warp & 3) * 32;
    int wn = (warp >> 2) * 32;

    float acc[2][4][4];
#pragma unroll
    for (int i = 0; i < 2; i++)
#pragma unroll
        for (int j = 0; j < 4; j++)
#pragma unroll
            for (int k = 0; k < 4; k++) acc[i][j][k] = 0.f;

    unsigned sbase = (unsigned)__cvta_generic_to_shared(smraw);

#pragma unroll
    for (int p = 0; p < 2; p++) {
        int k0 = p * 16;
#pragma unroll
        for (int c = tid; c < 512; c += 256) {
            int kr = c >> 5, seg = c & 31;
            cpa16(sbase + p * OBUF + kr * 544 + seg * 16,
                  A + (size_t)(k0 + kr) * NTOK + t0 + seg * 4);
        }
        {
            int kr = tid >> 4, seg = tid & 15;
            cpa16(sbase + p * OBUF + 8704 + kr * 288 + seg * 16,
                  Wt + (size_t)(k0 + kr) * CDIM + c0 + seg * 4);
        }
        CP_COMMIT();
    }

    for (int kit = 0; kit < CDIM / 16; kit++) {
        CP_WAIT1();
        __syncthreads();
        int p = kit % 3;

        int k2 = (kit + 2) * 16;
        if (k2 < CDIM) {
            int pn = (kit + 2) % 3;
#pragma unroll
            for (int c = tid; c < 512; c += 256) {
                int kr = c >> 5, seg = c & 31;
                cpa16(sbase + pn * OBUF + kr * 544 + seg * 16,
                      A + (size_t)(k2 + kr) * NTOK + t0 + seg * 4);
            }
            int kr = tid >> 4, seg = tid & 15;
            cpa16(sbase + pn * OBUF + 8704 + kr * 288 + seg * 16,
                  Wt + (size_t)(k2 + kr) * CDIM + c0 + seg * 4);
        }
        CP_COMMIT();

        float* As = (float*)(smraw + p * OBUF);
        float* Bs = As + 2176;

#pragma unroll
        for (int ks = 0; ks < 2; ks++) {
            int k8 = ks * 8;
            float a[2][4], bb[4][2];
#pragma unroll
            for (int ms = 0; ms < 2; ms++) {
                int ml = wm + ms * 16;
                a[ms][0] = tf32r(As[(k8 + q) * ASTR + ml + r]);
                a[ms][1] = tf32r(As[(k8 + q) * ASTR + ml + r + 8]);
                a[ms][2] = tf32r(As[(k8 + q + 4) * ASTR + ml + r]);
                a[ms][3] = tf32r(As[(k8 + q + 4) * ASTR + ml + r + 8]);
            }
#pragma unroll
            for (int ns = 0; ns < 4; ns++) {
                int nl = wn + ns * 8;
                bb[ns][0] = tf32r(Bs[(k8 + q) * BSTR + nl + r]);
                bb[ns][1] = tf32r(Bs[(k8 + q + 4) * BSTR + nl + r]);
            }
#pragma unroll
            for (int ms = 0; ms < 2; ms++)
#pragma unroll
                for (int ns = 0; ns < 4; ns++)
                    mma_tf32(acc[ms][ns][0], acc[ms][ns][1], acc[ms][ns][2], acc[ms][ns][3],
                             a[ms][0], a[ms][1], a[ms][2], a[ms][3],
                             bb[ns][0], bb[ns][1]);
        }
    }

#pragma unroll
    for (int ns = 0; ns < 4; ns++) {
        float2 bi = *(const float2*)&bias[c0 + wn + ns * 8 + 2 * q];
#pragma unroll
        for (int ms = 0; ms < 2; ms++) {
            acc[ms][ns][0] += bi.x; acc[ms][ns][1] += bi.y;
            acc[ms][ns][2] += bi.x; acc[ms][ns][3] += bi.y;
        }
    }

    CP_WAIT0();
    __syncthreads();
#pragma unroll
    for (int ms = 0; ms < 2; ms++) {
        int rowL = wm + ms * 16 + r;
#pragma unroll
        for (int ns = 0; ns < 4; ns++) {
            int chL = wn + ns * 8 + 2 * q;
            Cs[rowL * 65 + chL]           = acc[ms][ns][0];
            Cs[rowL * 65 + chL + 1]       = acc[ms][ns][1];
            Cs[(rowL + 8) * 65 + chL]     = acc[ms][ns][2];
            Cs[(rowL + 8) * 65 + chL + 1] = acc[ms][ns][3];
        }
    }
    __syncthreads();
    for (int e = tid; e < 8192; e += 256) {
        int cL = e >> 7, nL = e & 127;
        size_t idx = ((size_t)b * CDIM + c0 + cL) * NTOK + t0 + nL;
        outp[idx] = Cs[nL * 65 + cL] + resid[idx];
    }
}

// ---------------- attention: ldmatrix frags, 3-stage, one sync/iter ---------
#define KW 36      // row stride in 32-bit words (144 B)
#define BUFB 18432
#define ONES2 0x3C003C00u   // f16x2 {1.0, 1.0}

__global__ void __launch_bounds__(128) k_attn()
{
    extern __shared__ __align__(16) unsigned char smraw[];   // 3*BUFB dynamic
    unsigned* Qw = (unsigned*)smraw;                 // [128][KW] (pre-loop only)
    float*    Es = (float*)smraw;                    // [64][71]  (epilogue only)

    int tid  = threadIdx.x;
    int lane = tid & 31, warp = tid >> 5;
    int r = lane >> 2, q = lane & 3;
    int n0 = blockIdx.x * 128;
    int h  = blockIdx.y;
    int b  = blockIdx.z;

    // ---- stage Q (bf16, pre-scaled by log2e/8 in GEMM) ----
    {
        const __nv_bfloat16* Qg = g_qb + ((size_t)b * NTOK + n0) * CDIM + h * HD;
#pragma unroll
        for (int it = 0; it < 8; it++) {
            uint4 v = *(const uint4*)&Qg[(size_t)tid * CDIM + it * 8];
            *(uint4*)&Qw[tid * KW + it * 4] = v;
        }
    }
    __syncthreads();

    unsigned aq[2][4][4];
#pragma unroll
    for (int mf = 0; mf < 2; mf++) {
        int rb = warp * 32 + mf * 16 + r;
#pragma unroll
        for (int kt = 0; kt < 4; kt++) {
            int base = kt * 8 + q;
            aq[mf][kt][0] = Qw[rb * KW + base];
            aq[mf][kt][1] = Qw[(rb + 8) * KW + base];
            aq[mf][kt][2] = Qw[rb * KW + base + 4];
            aq[mf][kt][3] = Qw[(rb + 8) * KW + base + 4];
        }
    }
    __syncthreads();

    float o[2][8][4];
#pragma unroll
    for (int mf = 0; mf < 2; mf++)
#pragma unroll
        for (int i = 0; i < 8; i++)
#pragma unroll
            for (int j = 0; j < 4; j++) o[mf][i][j] = 0.f;
    float lacc[2][4];
#pragma unroll
    for (int mf = 0; mf < 2; mf++)
#pragma unroll
        for (int j = 0; j < 4; j++) lacc[mf][j] = 0.f;

    const __nv_bfloat16* Kg = g_kb + (size_t)b * NTOK * CDIM + h * HD;
    const __half*        Vg = g_vh + ((size_t)b * CDIM + h * HD) * NTOK;

    int srow = tid >> 1, sh = tid & 1;
    unsigned sbase = (unsigned)__cvta_generic_to_shared(smraw);
    unsigned doff = srow * 144 + sh * 64;

    unsigned boff = (((lane >> 4) & 1) * 8 + (lane & 7)) * 144 + ((lane >> 3) & 1) * 16;

    // prefetch tiles 0 and 1
#pragma unroll
    for (int p = 0; p < 2; p++) {
        unsigned kd = sbase + p * BUFB + doff;
        const __nv_bfloat16* ksrc = Kg + (size_t)(p * 64 + srow) * CDIM + sh * 32;
        const __half*        vsrc = Vg + (size_t)srow * NTOK + p * 64 + sh * 32;
#pragma unroll
        for (int j = 0; j < 4; j++) {
            cpa16(kd + j * 16, ksrc + j * 8);
            cpa16(kd + 9216 + j * 16, vsrc + j * 8);
        }
        CP_COMMIT();
    }

    for (int it = 0; it < NTOK / 64; it++) {
        CP_WAIT1();
        __syncthreads();
        unsigned bufK = sbase + (it % 3) * BUFB;

        int jn = (it + 2) * 64;
        if (jn < NTOK) {
            unsigned kd = sbase + ((it + 2) % 3) * BUFB + doff;
            const __nv_bfloat16* ksrc = Kg + (size_t)(jn + srow) * CDIM + sh * 32;
            const __half*        vsrc = Vg + (size_t)srow * NTOK + jn + sh * 32;
#pragma unroll
            for (int j = 0; j < 4; j++) {
                cpa16(kd + j * 16, ksrc + j * 8);
                cpa16(kd + 9216 + j * 16, vsrc + j * 8);
            }
        }
        CP_COMMIT();

        // ---- S = Q * K^T (log2 space); K frags via ldmatrix.x4 ----
        float s[2][8][4];
#pragma unroll
        for (int mf = 0; mf < 2; mf++)
#pragma unroll
            for (int i = 0; i < 8; i++)
#pragma unroll
                for (int j = 0; j < 4; j++) s[mf][i][j] = 0.f;

#pragma unroll
        for (int kt = 0; kt < 4; kt++) {
            unsigned kab = bufK + kt * 32 + boff;
#pragma unroll
            for (int p = 0; p < 4; p++) {
                unsigned b0a, b1a, b0b, b1b;
                ldsm4(b0a, b1a, b0b, b1b, kab + p * 2304);
                mma_bf16(s[0][2*p][0], s[0][2*p][1], s[0][2*p][2], s[0][2*p][3],
                         aq[0][kt][0], aq[0][kt][1], aq[0][kt][2], aq[0][kt][3], b0a, b1a);
                mma_bf16(s[1][2*p][0], s[1][2*p][1], s[1][2*p][2], s[1][2*p][3],
                         aq[1][kt][0], aq[1][kt][1], aq[1][kt][2], aq[1][kt][3], b0a, b1a);
                mma_bf16(s[0][2*p+1][0], s[0][2*p+1][1], s[0][2*p+1][2], s[0][2*p+1][3],
                         aq[0][kt][0], aq[0][kt][1], aq[0][kt][2], aq[0][kt][3], b0b, b1b);
                mma_bf16(s[1][2*p+1][0], s[1][2*p+1][1], s[1][2*p+1][2], s[1][2*p+1][3],
                         aq[1][kt][0], aq[1][kt][1], aq[1][kt][2], aq[1][kt][3], b0b, b1b);
            }
        }

        // ---- P = exp2(S) packed f16; O += P*V; lacc += P*ones ----
#pragma unroll
        for (int kt = 0; kt < 4; kt++) {
            unsigned pa[2][4];
#pragma unroll
            for (int mf = 0; mf < 2; mf++) {
                pa[mf][0] = exp2h2(s[mf][2*kt][0],     s[mf][2*kt][1]);
                pa[mf][1] = exp2h2(s[mf][2*kt][2],     s[mf][2*kt][3]);
                pa[mf][2] = exp2h2(s[mf][2*kt + 1][0], s[mf][2*kt + 1][1]);
                pa[mf][3] = exp2h2(s[mf][2*kt + 1][2], s[mf][2*kt + 1][3]);
            }
            mma_f16(lacc[0][0], lacc[0][1], lacc[0][2], lacc[0][3],
                    pa[0][0], pa[0][1], pa[0][2], pa[0][3], ONES2, ONES2);
            mma_f16(lacc[1][0], lacc[1][1], lacc[1][2], lacc[1][3],
                    pa[1][0], pa[1][1], pa[1][2], pa[1][3], ONES2, ONES2);
            unsigned vab = bufK + 9216 + kt * 32 + boff;
#pragma unroll
            for (int p = 0; p < 4; p++) {
                unsigned v0a, v1a, v0b, v1b;
                ldsm4(v0a, v1a, v0b, v1b, vab + p * 2304);
                mma_f16(o[0][2*p][0], o[0][2*p][1], o[0][2*p][2], o[0][2*p][3],
                        pa[0][0], pa[0][1], pa[0][2], pa[0][3], v0a, v1a);
                mma_f16(o[1][2*p][0], o[1][2*p][1], o[1][2*p][2], o[1][2*p][3],
                        pa[1][0], pa[1][1], pa[1][2], pa[1][3], v0a, v1a);
                mma_f16(o[0][2*p+1][0], o[0][2*p+1][1], o[0][2*p+1][2], o[0][2*p+1][3],
                        pa[0][0], pa[0][1], pa[0][2], pa[0][3], v0b, v1b);
                mma_f16(o[1][2*p+1][0], o[1][2*p+1][1], o[1][2*p+1][2], o[1][2*p+1][3],
                        pa[1][0], pa[1][1], pa[1][2], pa[1][3], v0b, v1b);
            }
        }
    }

    CP_WAIT0();
    __syncthreads();

    // ---- epilogue: normalize, two-phase smem transpose, write [B][C][N] ----
#pragma unroll
    for (int ph = 0; ph < 2; ph++) {
        if ((warp >> 1) == ph) {
#pragma unroll
            for (int mf = 0; mf < 2; mf++) {
                int rowL = (warp & 1) * 32 + mf * 16 + r;
                float il0 = 1.0f / lacc[mf][0], il1 = 1.0f / lacc[mf][2];
#pragma unroll
                for (int ct = 0; ct < 8; ct++) {
                    int cc = ct * 8 + 2 * q;
                    Es[rowL * 71 + cc]           = o[mf][ct][0] * il0;
                    Es[rowL * 71 + cc + 1]       = o[mf][ct][1] * il0;
                    Es[(rowL + 8) * 71 + cc]     = o[mf][ct][2] * il1;
                    Es[(rowL + 8) * 71 + cc + 1] = o[mf][ct][3] * il1;
                }
            }
        }
        __syncthreads();
        for (int e = tid; e < 4096; e += 128) {
            int c = e >> 6, n = e & 63;
            g_o[((size_t)b * CDIM + h * HD + c) * NTOK + n0 + ph * 64 + n] = Es[n * 71 + c];
        }
        __syncthreads();
    }
}

// ---------------- launch ----------------------------------------------------
extern "C" void kernel_launch(void* const* d_in, const int* in_sizes, int n_in,
                              void* d_out, int out_size)
{
    const float* x     = (const float*)d_in[0];
    const float* gamma = (const float*)d_in[1];
    const float* beta  = (const float*)d_in[2];
    const float* Wq    = (const float*)d_in[3];
    const float* bq    = (const float*)d_in[4];
    const float* Wk    = (const float*)d_in[5];
    const float* bk    = (const float*)d_in[6];
    const float* Wv    = (const float*)d_in[7];
    const float* bv    = (const float*)d_in[8];
    const float* Wo    = (const float*)d_in[9];
    const float* bo    = (const float*)d_in[10];
    float* out = (float*)d_out;

    const float SCL = 0.125f * 1.4426950408889634f;   // (1/sqrt(hd)) * log2(e)

    static int attr_done = 0;
    if (!attr_done) {
        cudaFuncSetAttribute(k_qkv,  cudaFuncAttributeMaxDynamicSharedMemorySize, 3 * QSTG);
        cudaFuncSetAttribute(k_attn, cudaFuncAttributeMaxDynamicSharedMemorySize, 3 * BUFB);
        attr_done = 1;
    }

    k_prep<<<64 + 1024, 256>>>(x, gamma, beta, Wq, Wk, Wv, Wo);

    k_qkv<<<dim3(NTOK/128, CDIM/64, BATCH), 256, 3 * QSTG>>>(bq, bk, bv, SCL);

    k_attn<<<dim3(NTOK / 128, HEADS, BATCH), 128, 3 * BUFB>>>();

    k_gemm_out<<<dim3(NTOK/128, CDIM/64, BATCH), 256>>>(bo, x, out);
}

// round 15
// speedup vs baseline: 1.1352x; 1.0758x over previous
#include <cuda_runtime.h>
#include <cuda_bf16.h>
#include <cuda_fp16.h>
#include <math.h>

#define BATCH  2
#define CDIM   512
#define NTOK   4096
#define HEADS  8
#define HD     64
#define GROUPS 32

// ---------------- scratch (static device globals; no allocations) ----------
__device__ __nv_bfloat16 g_hb[(size_t)BATCH*NTOK*CDIM];   // GN out, [B][N][C]
__device__ __nv_bfloat16 g_qb[(size_t)BATCH*NTOK*CDIM];   // Q (pre-scaled), [B][N][C]
__device__ __nv_bfloat16 g_kb[(size_t)BATCH*NTOK*CDIM];   // K, [B][N][C]
__device__ __half        g_vh[(size_t)BATCH*CDIM*NTOK];   // V, [B][C][N], f16
__device__ __nv_bfloat16 g_ob[(size_t)BATCH*NTOK*CDIM];   // attn out, [B][N][C] bf16
__device__ __nv_bfloat16 g_wb[4*(size_t)CDIM*CDIM];       // Wq,Wk,Wv,Wo bf16 [c][k]

// ---------------- helpers ---------------------------------------------------
__device__ __forceinline__ void mma_bf16(float& d0, float& d1, float& d2, float& d3,
                                         unsigned a0, unsigned a1, unsigned a2, unsigned a3,
                                         unsigned b0, unsigned b1)
{
    asm volatile("mma.sync.aligned.m16n8k16.row.col.f32.bf16.bf16.f32 "
                 "{%0,%1,%2,%3},{%4,%5,%6,%7},{%8,%9},{%0,%1,%2,%3};"
                 : "+f"(d0), "+f"(d1), "+f"(d2), "+f"(d3)
                 : "r"(a0), "r"(a1), "r"(a2), "r"(a3), "r"(b0), "r"(b1));
}

__device__ __forceinline__ void mma_f16(float& d0, float& d1, float& d2, float& d3,
                                        unsigned a0, unsigned a1, unsigned a2, unsigned a3,
                                        unsigned b0, unsigned b1)
{
    asm volatile("mma.sync.aligned.m16n8k16.row.col.f32.f16.f16.f32 "
                 "{%0,%1,%2,%3},{%4,%5,%6,%7},{%8,%9},{%0,%1,%2,%3};"
                 : "+f"(d0), "+f"(d1), "+f"(d2), "+f"(d3)
                 : "r"(a0), "r"(a1), "r"(a2), "r"(a3), "r"(b0), "r"(b1));
}

__device__ __forceinline__ void ldsm4(unsigned& r0, unsigned& r1, unsigned& r2,
                                      unsigned& r3, unsigned a)
{
    asm volatile("ldmatrix.sync.aligned.m8n8.x4.shared.b16 {%0,%1,%2,%3}, [%4];"
                 : "=r"(r0), "=r"(r1), "=r"(r2), "=r"(r3) : "r"(a));
}

__device__ __forceinline__ unsigned packbf(float lo, float hi) {
    __nv_bfloat162 p = __floats2bfloat162_rn(lo, hi);
    return *(unsigned*)&p;
}

// exp2 of two f32 values -> packed f16x2, via ONE MUFU instruction
__device__ __forceinline__ unsigned exp2h2(float lo, float hi) {
    unsigned d;
    asm("{\n\t.reg .b32 t;\n\t"
        "cvt.rn.f16x2.f32 t, %2, %1;\n\t"
        "ex2.approx.f16x2 %0, t;\n\t}"
        : "=r"(d) : "f"(lo), "f"(hi));
    return d;
}

__device__ __forceinline__ void cpa16(unsigned dst, const void* src) {
    asm volatile("cp.async.ca.shared.global [%0], [%1], 16;" :: "r"(dst), "l"(src));
}
#define CP_COMMIT() asm volatile("cp.async.commit_group;")
#define CP_WAIT1()  asm volatile("cp.async.wait_group 1;")
#define CP_WAIT0()  asm volatile("cp.async.wait_group 0;")

// ---------------- fused prep: GroupNorm (blocks 0..63) + weight bf16 --------
// blocks [0,64)        : GroupNorm for (b,g) = blockIdx.x
// blocks [64, 64+1024) : weight bf16 convert; z = tile / 256 selects Wq/Wk/Wv/Wo
__global__ void k_prep(const float* __restrict__ x,
                       const float* __restrict__ gamma,
                       const float* __restrict__ beta,
                       const float* __restrict__ W0, const float* __restrict__ W1,
                       const float* __restrict__ W2, const float* __restrict__ W3)
{
    __shared__ float red[18];
    int tid = threadIdx.x;

    if (blockIdx.x >= 64) {
        // ---- weight prep: 1024 tiles of 32x32, all native-layout bf16 ----
        int t = blockIdx.x - 64;
        int z = t >> 8;                   // 0..3
        int ti = t & 255;
        int bx = ti & 15, by = ti >> 4;
        int tx = tid & 31, ty = tid >> 5;
        const float* srcs[4] = {W0, W1, W2, W3};
        const float* W = srcs[z];
        __nv_bfloat16* dst = g_wb + (size_t)z * CDIM * CDIM;
        int xx = bx * 32 + tx, yy = by * 32 + ty;
#pragma unroll
        for (int i = 0; i < 32; i += 8)
            dst[(size_t)(yy + i) * CDIM + xx] =
                __float2bfloat16(W[(size_t)(yy + i) * CDIM + xx]);
        return;
    }

    // ---- GroupNorm for (b, g) ----
    int b = blockIdx.x >> 5;
    int g = blockIdx.x & 31;
    size_t base = ((size_t)b * CDIM + g * 16) * NTOK;
    const float4* xp = (const float4*)(x + base);

    float s = 0.f, ss = 0.f;
    for (int i = tid; i < 16384; i += 256) {
        float4 v = xp[i];
        s  += v.x + v.y + v.z + v.w;
        ss += v.x*v.x + v.y*v.y + v.z*v.z + v.w*v.w;
    }
#pragma unroll
    for (int off = 16; off > 0; off >>= 1) {
        s  += __shfl_xor_sync(0xffffffffu, s,  off);
        ss += __shfl_xor_sync(0xffffffffu, ss, off);
    }
    int warp = tid >> 5;
    if ((tid & 31) == 0) { red[warp] = s; red[8 + warp] = ss; }
    __syncthreads();
    if (tid == 0) {
        float S = 0.f, SS = 0.f;
        for (int w = 0; w < 8; w++) { S += red[w]; SS += red[8 + w]; }
        float mean = S * (1.0f / 65536.0f);
        float var  = SS * (1.0f / 65536.0f) - mean * mean;
        red[16] = mean;
        red[17] = rsqrtf(var + 1e-5f);
    }
    __syncthreads();
    float mean = red[16], rstd = red[17];

    float ga[16], be[16];
#pragma unroll
    for (int c = 0; c < 16; c++) {
        ga[c] = gamma[g * 16 + c] * rstd;
        be[c] = beta[g * 16 + c] - mean * ga[c];
    }

    const float* xc = x + base;
    __nv_bfloat16* hb = g_hb + (size_t)b * NTOK * CDIM + g * 16;
    for (int t = tid; t < NTOK; t += 256) {
        unsigned w[8];
#pragma unroll
        for (int c2 = 0; c2 < 8; c2++) {
            float v0 = xc[(size_t)(2 * c2) * NTOK + t];
            float v1 = xc[(size_t)(2 * c2 + 1) * NTOK + t];
            w[c2] = packbf(v0 * ga[2 * c2] + be[2 * c2],
                           v1 * ga[2 * c2 + 1] + be[2 * c2 + 1]);
        }
        uint4* dst = (uint4*)(hb + (size_t)t * CDIM);
        dst[0] = make_uint4(w[0], w[1], w[2], w[3]);
        dst[1] = make_uint4(w[4], w[5], w[6], w[7]);
    }
}

// ---------------- fused QKV GEMM (bf16, K-tile 32, 3 stages, ldmatrix) ------
#define QSTG 25600

__device__ __forceinline__ void qkv_stage(unsigned sbase, const __nv_bfloat16* A,
                                          int t0, int c0, int k0, int bf, int tid)
{
    unsigned dst = sbase + bf * QSTG;
    int row = tid >> 1, hf = tid & 1;
    const __nv_bfloat16* as = A + (size_t)(t0 + row) * CDIM + k0 + hf * 16;
    cpa16(dst + row * 80 + hf * 32, as);
    cpa16(dst + row * 80 + hf * 32 + 16, as + 8);
#pragma unroll
    for (int c = tid; c < 768; c += 256) {
        int wi = c >> 8, idx = c & 255, rr = idx >> 2, ch = idx & 3;
        cpa16(dst + 10240 + wi * 5120 + rr * 80 + ch * 16,
              g_wb + (size_t)wi * CDIM * CDIM + (size_t)(c0 + rr) * CDIM + k0 + ch * 8);
    }
}

__global__ void __launch_bounds__(256) k_qkv(const float* __restrict__ bq,
                                             const float* __restrict__ bk,
                                             const float* __restrict__ bv,
                                             float scl)
{
    extern __shared__ __align__(16) unsigned char smraw[];   // 3*QSTG dynamic
    float* Cs = (float*)smraw;

    int b  = blockIdx.z;
    int t0 = blockIdx.x * 128;
    int c0 = blockIdx.y * 64;

    const __nv_bfloat16* A = g_hb + (size_t)b * NTOK * CDIM;   // [t][k]

    int tid  = threadIdx.x;
    int lane = tid & 31, warp = tid >> 5;
    int r = lane >> 2, q = lane & 3;
    int wm = (warp & 3) * 32;
    int wn = (warp >> 2) * 32;

    float acc[3][2][4][4];
#pragma unroll
    for (int w = 0; w < 3; w++)
#pragma unroll
        for (int i = 0; i < 2; i++)
#pragma unroll
            for (int j = 0; j < 4; j++)
#pragma unroll
                for (int k = 0; k < 4; k++) acc[w][i][j][k] = 0.f;

    unsigned sbase = (unsigned)__cvta_generic_to_shared(smraw);

    unsigned aoff = ((lane & 7) + ((lane >> 3) & 1) * 8) * 80 + ((lane >> 4) & 1) * 16;
    unsigned woff = (((lane >> 4) & 1) * 8 + (lane & 7)) * 80 + ((lane >> 3) & 1) * 16;

    qkv_stage(sbase, A, t0, c0, 0,  0, tid); CP_COMMIT();
    qkv_stage(sbase, A, t0, c0, 32, 1, tid); CP_COMMIT();

    for (int kit = 0; kit < CDIM / 32; kit++) {
        CP_WAIT1();
        __syncthreads();

        int k2 = (kit + 2) * 32;
        if (k2 < CDIM)
            qkv_stage(sbase, A, t0, c0, k2, (kit + 2) % 3, tid);
        CP_COMMIT();

        unsigned bufb = sbase + (kit % 3) * QSTG;
#pragma unroll
        for (int ks = 0; ks < 2; ks++) {
            unsigned a[2][4];
#pragma unroll
            for (int ms = 0; ms < 2; ms++)
                ldsm4(a[ms][0], a[ms][1], a[ms][2], a[ms][3],
                      bufb + (wm + ms * 16) * 80 + ks * 32 + aoff);
#pragma unroll
            for (int wi = 0; wi < 3; wi++) {
#pragma unroll
                for (int np = 0; np < 2; np++) {
                    unsigned w0, w1, w2, w3;
                    ldsm4(w0, w1, w2, w3,
                          bufb + 10240 + wi * 5120 + (wn + np * 16) * 80 + ks * 32 + woff);
#pragma unroll
                    for (int ms = 0; ms < 2; ms++) {
                        mma_bf16(acc[wi][ms][2*np][0], acc[wi][ms][2*np][1],
                                 acc[wi][ms][2*np][2], acc[wi][ms][2*np][3],
                                 a[ms][0], a[ms][1], a[ms][2], a[ms][3], w0, w1);
                        mma_bf16(acc[wi][ms][2*np+1][0], acc[wi][ms][2*np+1][1],
                                 acc[wi][ms][2*np+1][2], acc[wi][ms][2*np+1][3],
                                 a[ms][0], a[ms][1], a[ms][2], a[ms][3], w2, w3);
                    }
                }
            }
        }
    }

    // ---- Q and K: direct row-major bf16 stores ----
#pragma unroll
    for (int wi = 0; wi < 2; wi++) {
        const float* bias = (wi == 0 ? bq : bk);
        float osc = (wi == 0 ? scl : 1.0f);
        __nv_bfloat16* Y = (wi == 0 ? g_qb : g_kb);
#pragma unroll
        for (int nt = 0; nt < 4; nt++) {
            float2 bi = *(const float2*)&bias[c0 + wn + nt * 8 + 2 * q];
#pragma unroll
            for (int ms = 0; ms < 2; ms++) {
                size_t row0 = (size_t)b * NTOK + t0 + wm + ms * 16 + r;
                int ch = c0 + wn + nt * 8 + 2 * q;
                *(__nv_bfloat162*)&Y[row0 * CDIM + ch] =
                    __floats2bfloat162_rn((acc[wi][ms][nt][0] + bi.x) * osc,
                                          (acc[wi][ms][nt][1] + bi.y) * osc);
                *(__nv_bfloat162*)&Y[(row0 + 8) * CDIM + ch] =
                    __floats2bfloat162_rn((acc[wi][ms][nt][2] + bi.x) * osc,
                                          (acc[wi][ms][nt][3] + bi.y) * osc);
            }
        }
    }

    // ---- V: smem-staged transpose to [B][C][N] f16 ----
    CP_WAIT0();
    __syncthreads();
#pragma unroll
    for (int ms = 0; ms < 2; ms++) {
        int rowL = wm + ms * 16 + r;
#pragma unroll
        for (int nt = 0; nt < 4; nt++) {
            int chL = wn + nt * 8 + 2 * q;
            float2 bi = *(const float2*)&bv[c0 + chL];
            Cs[rowL * 65 + chL]           = acc[2][ms][nt][0] + bi.x;
            Cs[rowL * 65 + chL + 1]       = acc[2][ms][nt][1] + bi.y;
            Cs[(rowL + 8) * 65 + chL]     = acc[2][ms][nt][2] + bi.x;
            Cs[(rowL + 8) * 65 + chL + 1] = acc[2][ms][nt][3] + bi.y;
        }
    }
    __syncthreads();
    for (int e = tid; e < 8192; e += 256) {
        int cL = e >> 7, nL = e & 127;
        g_vh[((size_t)b * CDIM + c0 + cL) * NTOK + t0 + nL] =
            __float2half(Cs[nL * 65 + cL]);
    }
}

// ---------------- output GEMM (bf16, k_qkv-style, single weight Wo) ---------
// out[b][c][n] = x[b][c][n] + sum_k o[b][n][k] * Wo[c][k] + bo[c]
#define OSTG 15360   // A 128*80 + W 64*80

__device__ __forceinline__ void out_stage(unsigned sbase, const __nv_bfloat16* A,
                                          int t0, int c0, int k0, int bf, int tid)
{
    unsigned dst = sbase + bf * OSTG;
    int row = tid >> 1, hf = tid & 1;
    const __nv_bfloat16* as = A + (size_t)(t0 + row) * CDIM + k0 + hf * 16;
    cpa16(dst + row * 80 + hf * 32, as);
    cpa16(dst + row * 80 + hf * 32 + 16, as + 8);
    {
        int rr = tid >> 2, ch = tid & 3;
        cpa16(dst + 10240 + rr * 80 + ch * 16,
              g_wb + 3 * (size_t)CDIM * CDIM + (size_t)(c0 + rr) * CDIM + k0 + ch * 8);
    }
}

__global__ void __launch_bounds__(256) k_gemm_out(const float* __restrict__ bias,
                                                  const float* __restrict__ resid,
                                                  float* __restrict__ outp)
{
    extern __shared__ __align__(16) unsigned char smraw[];   // 3*OSTG dynamic
    float* Cs = (float*)smraw;                               // [128][65] epilogue

    int b  = blockIdx.z;
    int t0 = blockIdx.x * 128;
    int c0 = blockIdx.y * 64;

    const __nv_bfloat16* A = g_ob + (size_t)b * NTOK * CDIM;   // [t][k]

    int tid  = threadIdx.x;
    int lane = tid & 31, warp = tid >> 5;
    int r = lane >> 2, q = lane & 3;
    int wm = (warp & 3) * 32;
    int wn = (warp >> 2) * 32;

    float acc[2][4][4];
#pragma unroll
    for (int i = 0; i < 2; i++)
#pragma unroll
        for (int j = 0; j < 4; j++)
#pragma unroll
            for (int k = 0; k < 4; k++) acc[i][j][k] = 0.f;

    unsigned sbase = (unsigned)__cvta_generic_to_shared(smraw);

    unsigned aoff = ((lane & 7) + ((lane >> 3) & 1) * 8) * 80 + ((lane >> 4) & 1) * 16;
    unsigned woff = (((lane >> 4) & 1) * 8 + (lane & 7)) * 80 + ((lane >> 3) & 1) * 16;

    out_stage(sbase, A, t0, c0, 0,  0, tid); CP_COMMIT();
    out_stage(sbase, A, t0, c0, 32, 1, tid); CP_COMMIT();

    for (int kit = 0; kit < CDIM / 32; kit++) {
        CP_WAIT1();
        __syncthreads();

        int k2 = (kit + 2) * 32;
        if (k2 < CDIM)
            out_stage(sbase, A, t0, c0, k2, (kit + 2) % 3, tid);
        CP_COMMIT();

        unsigned bufb = sbase + (kit % 3) * OSTG;
#pragma unroll
        for (int ks = 0; ks < 2; ks++) {
            unsigned a[2][4];
#pragma unroll
            for (int ms = 0; ms < 2; ms++)
                ldsm4(a[ms][0], a[ms][1], a[ms][2], a[ms][3],
                      bufb + (wm + ms * 16) * 80 + ks * 32 + aoff);
#pragma unroll
            for (int np = 0; np < 2; np++) {
                unsigned w0, w1, w2, w3;
                ldsm4(w0, w1, w2, w3,
                      bufb + 10240 + (wn + np * 16) * 80 + ks * 32 + woff);
#pragma unroll
                for (int ms = 0; ms < 2; ms++) {
                    mma_bf16(acc[ms][2*np][0], acc[ms][2*np][1],
                             acc[ms][2*np][2], acc[ms][2*np][3],
                             a[ms][0], a[ms][1], a[ms][2], a[ms][3], w0, w1);
                    mma_bf16(acc[ms][2*np+1][0], acc[ms][2*np+1][1],
                             acc[ms][2*np+1][2], acc[ms][2*np+1][3],
                             a[ms][0], a[ms][1], a[ms][2], a[ms][3], w2, w3);
                }
            }
        }
    }

    // ---- epilogue: bias, stage [t][c], write transposed [B][C][N] + resid --
    CP_WAIT0();
    __syncthreads();
#pragma unroll
    for (int ms = 0; ms < 2; ms++) {
        int rowL = wm + ms * 16 + r;
#pragma unroll
        for (int nt = 0; nt < 4; nt++) {
            int chL = wn + nt * 8 + 2 * q;
            float2 bi = *(const float2*)&bias[c0 + chL];
            Cs[rowL * 65 + chL]           = acc[ms][nt][0] + bi.x;
            Cs[rowL * 65 + chL + 1]       = acc[ms][nt][1] + bi.y;
            Cs[(rowL + 8) * 65 + chL]     = acc[ms][nt][2] + bi.x;
            Cs[(rowL + 8) * 65 + chL + 1] = acc[ms][nt][3] + bi.y;
        }
    }
    __syncthreads();
    for (int e = tid; e < 8192; e += 256) {
        int cL = e >> 7, nL = e & 127;
        size_t idx = ((size_t)b * CDIM + c0 + cL) * NTOK + t0 + nL;
        outp[idx] = Cs[nL * 65 + cL] + resid[idx];
    }
}

// ---------------- attention: ldmatrix frags, 3-stage, direct bf16 out -------
#define KW 36      // row stride in 32-bit words (144 B)
#define BUFB 18432
#define ONES2 0x3C003C00u   // f16x2 {1.0, 1.0}

__global__ void __launch_bounds__(128) k_attn()
{
    extern __shared__ __align__(16) unsigned char smraw[];   // 3*BUFB dynamic
    unsigned* Qw = (unsigned*)smraw;                 // [128][KW] (pre-loop only)

    int tid  = threadIdx.x;
    int lane = tid & 31, warp = tid >> 5;
    int r = lane >> 2, q = lane & 3;
    int n0 = blockIdx.x * 128;
    int h  = blockIdx.y;
    int b  = blockIdx.z;

    // ---- stage Q (bf16, pre-scaled by log2e/8 in GEMM) ----
    {
        const __nv_bfloat16* Qg = g_qb + ((size_t)b * NTOK + n0) * CDIM + h * HD;
#pragma unroll
        for (int it = 0; it < 8; it++) {
            uint4 v = *(const uint4*)&Qg[(size_t)tid * CDIM + it * 8];
            *(uint4*)&Qw[tid * KW + it * 4] = v;
        }
    }
    __syncthreads();

    unsigned aq[2][4][4];
#pragma unroll
    for (int mf = 0; mf < 2; mf++) {
        int rb = warp * 32 + mf * 16 + r;
#pragma unroll
        for (int kt = 0; kt < 4; kt++) {
            int base = kt * 8 + q;
            aq[mf][kt][0] = Qw[rb * KW + base];
            aq[mf][kt][1] = Qw[(rb + 8) * KW + base];
            aq[mf][kt][2] = Qw[rb * KW + base + 4];
            aq[mf][kt][3] = Qw[(rb + 8) * KW + base + 4];
        }
    }
    __syncthreads();

    float o[2][8][4];
#pragma unroll
    for (int mf = 0; mf < 2; mf++)
#pragma unroll
        for (int i = 0; i < 8; i++)
#pragma unroll
            for (int j = 0; j < 4; j++) o[mf][i][j] = 0.f;
    float lacc[2][4];
#pragma unroll
    for (int mf = 0; mf < 2; mf++)
#pragma unroll
        for (int j = 0; j < 4; j++) lacc[mf][j] = 0.f;

    const __nv_bfloat16* Kg = g_kb + (size_t)b * NTOK * CDIM + h * HD;
    const __half*        Vg = g_vh + ((size_t)b * CDIM + h * HD) * NTOK;

    int srow = tid >> 1, sh = tid & 1;
    unsigned sbase = (unsigned)__cvta_generic_to_shared(smraw);
    unsigned doff = srow * 144 + sh * 64;

    unsigned boff = (((lane >> 4) & 1) * 8 + (lane & 7)) * 144 + ((lane >> 3) & 1) * 16;

    // prefetch tiles 0 and 1
#pragma unroll
    for (int p = 0; p < 2; p++) {
        unsigned kd = sbase + p * BUFB + doff;
        const __nv_bfloat16* ksrc = Kg + (size_t)(p * 64 + srow) * CDIM + sh * 32;
        const __half*        vsrc = Vg + (size_t)srow * NTOK + p * 64 + sh * 32;
#pragma unroll
        for (int j = 0; j < 4; j++) {
            cpa16(kd + j * 16, ksrc + j * 8);
            cpa16(kd + 9216 + j * 16, vsrc + j * 8);
        }
        CP_COMMIT();
    }

    for (int it = 0; it < NTOK / 64; it++) {
        CP_WAIT1();
        __syncthreads();
        unsigned bufK = sbase + (it % 3) * BUFB;

        int jn = (it + 2) * 64;
        if (jn < NTOK) {
            unsigned kd = sbase + ((it + 2) % 3) * BUFB + doff;
            const __nv_bfloat16* ksrc = Kg + (size_t)(jn + srow) * CDIM + sh * 32;
            const __half*        vsrc = Vg + (size_t)srow * NTOK + jn + sh * 32;
#pragma unroll
            for (int j = 0; j < 4; j++) {
                cpa16(kd + j * 16, ksrc + j * 8);
                cpa16(kd + 9216 + j * 16, vsrc + j * 8);
            }
        }
        CP_COMMIT();

        // ---- S = Q * K^T (log2 space); K frags via ldmatrix.x4 ----
        float s[2][8][4];
#pragma unroll
        for (int mf = 0; mf < 2; mf++)
#pragma unroll
            for (int i = 0; i < 8; i++)
#pragma unroll
                for (int j = 0; j < 4; j++) s[mf][i][j] = 0.f;

#pragma unroll
        for (int kt = 0; kt < 4; kt++) {
            unsigned kab = bufK + kt * 32 + boff;
#pragma unroll
            for (int p = 0; p < 4; p++) {
                unsigned b0a, b1a, b0b, b1b;
                ldsm4(b0a, b1a, b0b, b1b, kab + p * 2304);
                mma_bf16(s[0][2*p][0], s[0][2*p][1], s[0][2*p][2], s[0][2*p][3],
                         aq[0][kt][0], aq[0][kt][1], aq[0][kt][2], aq[0][kt][3], b0a, b1a);
                mma_bf16(s[1][2*p][0], s[1][2*p][1], s[1][2*p][2], s[1][2*p][3],
                         aq[1][kt][0], aq[1][kt][1], aq[1][kt][2], aq[1][kt][3], b0a, b1a);
                mma_bf16(s[0][2*p+1][0], s[0][2*p+1][1], s[0][2*p+1][2], s[0][2*p+1][3],
                         aq[0][kt][0], aq[0][kt][1], aq[0][kt][2], aq[0][kt][3], b0b, b1b);
                mma_bf16(s[1][2*p+1][0], s[1][2*p+1][1], s[1][2*p+1][2], s[1][2*p+1][3],
                         aq[1][kt][0], aq[1][kt][1], aq[1][kt][2], aq[1][kt][3], b0b, b1b);
            }
        }

        // ---- P = exp2(S) packed f16; O += P*V; lacc += P*ones ----
#pragma unroll
        for (int kt = 0; kt < 4; kt++) {
            unsigned pa[2][4];
#pragma unroll
            for (int mf = 0; mf < 2; mf++) {
                pa[mf][0] = exp2h2(s[mf][2*kt][0],     s[mf][2*kt][1]);
                pa[mf][1] = exp2h2(s[mf][2*kt][2],     s[mf][2*kt][3]);
                pa[mf][2] = exp2h2(s[mf][2*kt + 1][0], s[mf][2*kt + 1][1]);
                pa[mf][3] = exp2h2(s[mf][2*kt + 1][2], s[mf][2*kt + 1][3]);
            }
            mma_f16(lacc[0][0], lacc[0][1], lacc[0][2], lacc[0][3],
                    pa[0][0], pa[0][1], pa[0][2], pa[0][3], ONES2, ONES2);
            mma_f16(lacc[1][0], lacc[1][1], lacc[1][2], lacc[1][3],
                    pa[1][0], pa[1][1], pa[1][2], pa[1][3], ONES2, ONES2);
            unsigned vab = bufK + 9216 + kt * 32 + boff;
#pragma unroll
            for (int p = 0; p < 4; p++) {
                unsigned v0a, v1a, v0b, v1b;
                ldsm4(v0a, v1a, v0b, v1b, vab + p * 2304);
                mma_f16(o[0][2*p][0], o[0][2*p][1], o[0][2*p][2], o[0][2*p][3],
                        pa[0][0], pa[0][1], pa[0][2], pa[0][3], v0a, v1a);
                mma_f16(o[1][2*p][0], o[1][2*p][1], o[1][2*p][2], o[1][2*p][3],
                        pa[1][0], pa[1][1], pa[1][2], pa[1][3], v0a, v1a);
                mma_f16(o[0][2*p+1][0], o[0][2*p+1][1], o[0][2*p+1][2], o[0][2*p+1][3],
                        pa[0][0], pa[0][1], pa[0][2], pa[0][3], v0b, v1b);
                mma_f16(o[1][2*p+1][0], o[1][2*p+1][1], o[1][2*p+1][2], o[1][2*p+1][3],
                        pa[1][0], pa[1][1], pa[1][2], pa[1][3], v0b, v1b);
            }
        }
    }

    CP_WAIT0();

    // ---- epilogue: normalize, direct row-major bf16 stores to g_ob ----
    __nv_bfloat16* Og = g_ob + (size_t)b * NTOK * CDIM + h * HD;
#pragma unroll
    for (int mf = 0; mf < 2; mf++) {
        float il0 = 1.0f / lacc[mf][0], il1 = 1.0f / lacc[mf][2];
        size_t rowA = (size_t)(n0 + warp * 32 + mf * 16 + r);
#pragma unroll
        for (int ct = 0; ct < 8; ct++) {
            int cc = ct * 8 + 2 * q;
            *(__nv_bfloat162*)&Og[rowA * CDIM + cc] =
                __floats2bfloat162_rn(o[mf][ct][0] * il0, o[mf][ct][1] * il0);
            *(__nv_bfloat162*)&Og[(rowA + 8) * CDIM + cc] =
                __floats2bfloat162_rn(o[mf][ct][2] * il1, o[mf][ct][3] * il1);
        }
    }
}

// ---------------- launch ----------------------------------------------------
extern "C" void kernel_launch(void* const* d_in, const int* in_sizes, int n_in,
                              void* d_out, int out_size)
{
    const float* x     = (const float*)d_in[0];
    const float* gamma = (const float*)d_in[1];
    const float* beta  = (const float*)d_in[2];
    const float* Wq    = (const float*)d_in[3];
    const float* bq    = (const float*)d_in[4];
    const float* Wk    = (const float*)d_in[5];
    const float* bk    = (const float*)d_in[6];
    const float* Wv    = (const float*)d_in[7];
    const float* bv    = (const float*)d_in[8];
    const float* Wo    = (const float*)d_in[9];
    const float* bo    = (const float*)d_in[10];
    float* out = (float*)d_out;

    const float SCL = 0.125f * 1.4426950408889634f;   // (1/sqrt(hd)) * log2(e)

    static int attr_done = 0;
    if (!attr_done) {
        cudaFuncSetAttribute(k_qkv,      cudaFuncAttributeMaxDynamicSharedMemorySize, 3 * QSTG);
        cudaFuncSetAttribute(k_attn,     cudaFuncAttributeMaxDynamicSharedMemorySize, 3 * BUFB);
        cudaFuncSetAttribute(k_gemm_out, cudaFuncAttributeMaxDynamicSharedMemorySize, 3 * OSTG);
        attr_done = 1;
    }

    k_prep<<<64 + 1024, 256>>>(x, gamma, beta, Wq, Wk, Wv, Wo);

    k_qkv<<<dim3(NTOK/128, CDIM/64, BATCH), 256, 3 * QSTG>>>(bq, bk, bv, SCL);

    k_attn<<<dim3(NTOK / 128, HEADS, BATCH), 128, 3 * BUFB>>>();

    k_gemm_out<<<dim3(NTOK/128, CDIM/64, BATCH), 256, 3 * OSTG>>>(bo, x, out);
}